// round 12
// baseline (speedup 1.0000x reference)
#include <cuda_runtime.h>
#include <cuda_bf16.h>
#include <math.h>
#include <stdint.h>

// Problem constants (fixed by setup_inputs): B=32, N=M=1024, F=4
#define BB    32
#define NN    1024
#define MM    1024
#define CT    128             // threads per CTA (4 warps); cluster of 2 CTAs per batch
#define RR    4               // rows per thread (2*128*4 = 1024)
#define NG    (MM / 2)        // 512 column groups (2 cols per group)
#define NWL   4               // warps per CTA
#define GW    8               // global warps per batch (2 CTAs x 4)

// Epoch-skew parameters: barrier every KS steps; warp boundary gap = KS.
#define KS      8
#define WSKEW   (32 + KS - 1)                 // 39: sigma = lane + 39*gwarp
#define SIGMAX  (31 + WSKEW * (GW - 1))       // 304
#define STEPS   (NG + SIGMAX)                 // 816 (multiple of KS)
#define EPOCHS  (STEPS / KS)                  // 102

__device__ float g_loss[BB];
__device__ int   g_done;     // zero-init; self-resetting each launch

__device__ __forceinline__ float fsqrt_approx(float x) {
    float r;
    asm("sqrt.approx.f32 %0, %1;" : "=f"(r) : "f"(x));
    return r;
}

// Tag-synchronized 16B slot ops (tag travels with data in one v4 transaction).
__device__ __forceinline__ void xwait(unsigned addr, int tag, float& a, float& b, float& c) {
    int x, y, z, w;
    do {
        asm volatile("ld.volatile.shared.v4.b32 {%0,%1,%2,%3}, [%4];"
                     : "=r"(x), "=r"(y), "=r"(z), "=r"(w) : "r"(addr));
    } while (w != tag);
    a = __int_as_float(x); b = __int_as_float(y); c = __int_as_float(z);
}
__device__ __forceinline__ void xpost(uint64_t gaddr, float a, float b, float c, int tag) {
    asm volatile("st.volatile.v4.b32 [%0], {%1,%2,%3,%4};"
                 :: "l"(gaddr), "r"(__float_as_int(a)), "r"(__float_as_int(b)),
                    "r"(__float_as_int(c)), "r"(tag) : "memory");
}

__global__ __launch_bounds__(CT, 1) __cluster_dims__(2, 1, 1)
void dtw_fused(const float* __restrict__ preds, const float* __restrict__ targs,
               const float* __restrict__ subcoef, float* __restrict__ out)
{
    uint32_t rank;
    asm("mov.u32 %0, %%cluster_ctarank;" : "=r"(rank));
    const int b    = blockIdx.x >> 1;
    const int tid  = threadIdx.x;
    const int lane = tid & 31;
    const int warp = tid >> 5;
    const int gw   = (int)rank * NWL + warp;      // global warp 0..7
    const int sig  = lane + WSKEW * gw;           // thread skew
    const int T    = (int)rank * CT + tid;        // global thread: rows 4T..4T+3

    __shared__ float2 txy[MM];                    // 8 KB target basis
    __shared__ float4 sbD[2][KS][NWL];            // in-CTA D handoff
    __shared__ float4 sbA[2][KS][NWL];            // in-CTA A handoff
    __shared__ __align__(16) float4 xD[STEPS];    // 13 KB cross-CTA D slots (rank1 side)
    __shared__ __align__(16) float4 xA[STEPS];    // 13 KB cross-CTA A slots (rank1 side)

    const float* pb = preds + (size_t)b * NN * 4;
    const float* tb = targs + (size_t)b * MM * 4;
    const float INF = __int_as_float(0x7f800000);
    const float c0s = subcoef[0];
    const float c1s = subcoef[1];

    // ---- init smem ----
    for (int idx = tid; idx < MM; idx += CT)
        txy[idx] = *(const float2*)(tb + (size_t)idx * 4);
    for (int idx = tid; idx < 2 * KS * NWL; idx += CT) {
        ((float4*)sbD)[idx] = make_float4(INF, INF, INF, 0.0f);
        ((float4*)sbA)[idx] = make_float4(0.0f, 0.0f, 0.0f, 0.0f);
    }
    for (int idx = tid; idx < STEPS; idx += CT) {   // zero tags
        xD[idx] = make_float4(INF, INF, INF, 0.0f);
        xA[idx] = make_float4(0.0f, 0.0f, 0.0f, 0.0f);
    }

    float px[RR], py[RR], left[RR], Aleft[RR];
    #pragma unroll
    for (int q = 0; q < RR; ++q) {
        const float2 pv = *(const float2*)(pb + (size_t)(T * RR + q) * 4);
        px[q] = pv.x; py[q] = pv.y;
        left[q]  = INF;
        Aleft[q] = 0.0f;
    }
    __syncthreads();
    // Peer's slot init must complete before producer's first remote write.
    asm volatile("barrier.cluster.arrive.aligned;" ::: "memory");
    asm volatile("barrier.cluster.wait.aligned;" ::: "memory");

    // Producer-side remote addresses (rank0 lane31 warp3 posts into rank1's slots)
    uint64_t remD = 0, remA = 0;
    if (rank == 0) {
        uint64_t lD = (uint64_t)&xD[0], lA = (uint64_t)&xA[0];
        asm("mapa.u64 %0, %1, 1;" : "=l"(remD) : "l"(lD));
        asm("mapa.u64 %0, %1, 1;" : "=l"(remA) : "l"(lA));
    }
    const unsigned locD = (unsigned)__cvta_generic_to_shared(&xD[0]);
    const unsigned locA = (unsigned)__cvta_generic_to_shared(&xA[0]);

    // =====================================================================
    // Forward DP with loss propagation, split over a 2-CTA cluster:
    // thread owns rows 4T..4T+3; at step s it processes column group
    // g = s - sigma (columns 2g, 2g+1), carrying
    //   D[i,j] = cost(i,j) + min(D[i-1,j-1], D[i-1,j], D[i,j-1])
    //   A[i,j] = A[argmin parent] + |dx|*c0 + |dy|*c1
    // In-warp: 6 shfls (1-step gap). In-CTA warp boundary: KS-step gap via
    // double-buffered smem, one barrier per KS steps. Cross-CTA boundary
    // (gw 3 -> 4): write-once tag-synced DSMEM slots, gap = KS steps.
    // Answer = A at (NN-1, MM-1), held by rank1 thread CT-1 at the end.
    // =====================================================================
    float bot0 = INF, bot1 = INF, pb1 = INF;
    float Ab0  = 0.0f, Ab1 = 0.0f, Apb = 0.0f;

    float cst0[RR], cst1[RR], lc0[RR], lc1[RR];   // pipelined cost & loss terms
    {   // prologue: terms for step 0 (clamped group; unused if invalid)
        const int gc = min(max(0 - sig, 0), NG - 1);
        const float2 t0 = txy[2 * gc];
        const float2 t1 = txy[2 * gc + 1];
        #pragma unroll
        for (int q = 0; q < RR; ++q) {
            const float dx0 = px[q] - t0.x, dy0 = py[q] - t0.y;
            cst0[q] = fsqrt_approx(fmaf(dx0, dx0, dy0 * dy0));
            lc0[q]  = fmaf(fabsf(dy0), c1s, fabsf(dx0) * c0s);
            const float dx1 = px[q] - t1.x, dy1 = py[q] - t1.y;
            cst1[q] = fsqrt_approx(fmaf(dx1, dx1, dy1 * dy1));
            lc1[q]  = fmaf(fabsf(dy1), c1s, fabsf(dx1) * c0s);
        }
    }

    for (int e = 0; e < EPOCHS; ++e) {
        const int par = e & 1;
        #pragma unroll
        for (int ks = 0; ks < KS; ++ks) {
            const int s = e * KS + ks;

            float nb0 = __shfl_up_sync(0xffffffffu, bot0, 1);
            float nb1 = __shfl_up_sync(0xffffffffu, bot1, 1);
            float nbp = __shfl_up_sync(0xffffffffu, pb1, 1);
            float na0 = __shfl_up_sync(0xffffffffu, Ab0, 1);
            float na1 = __shfl_up_sync(0xffffffffu, Ab1, 1);
            float nap = __shfl_up_sync(0xffffffffu, Apb, 1);
            if (lane == 0) {
                if (gw == 0) {
                    nb0 = INF; nb1 = INF; nbp = INF;
                    na0 = 0.0f; na1 = 0.0f; nap = 0.0f;
                } else if (warp == 0) {
                    // cross-CTA consumer (rank1 warp0): producer step s-KS
                    if (s >= KS) {
                        const int sp = s - KS;
                        xwait(locD + sp * 16, sp + 1, nb0, nb1, nbp);
                        xwait(locA + sp * 16, sp + 1, na0, na1, nap);
                    } else {
                        nb0 = INF; nb1 = INF; nbp = INF;
                        na0 = 0.0f; na1 = 0.0f; nap = 0.0f;
                    }
                } else {
                    const float4 vD = sbD[par ^ 1][ks][warp - 1];  // producer step s-KS
                    nb0 = vD.x; nb1 = vD.y; nbp = vD.z;
                    const float4 vA = sbA[par ^ 1][ks][warp - 1];
                    na0 = vA.x; na1 = vA.y; nap = vA.z;
                }
            }

            const int g = s - sig;
            if ((unsigned)g < (unsigned)NG) {
                pb1 = bot1;   // bottom at c0-1 for next step's handoff
                Apb = Ab1;

                // ---- column c0 ----
                float up = nb0, dg = nbp, Aup = na0, Adg = nap;
                float cur0[RR], Acur0[RR];
                #pragma unroll
                for (int q = 0; q < RR; ++q) {
                    const float lf  = left[q];
                    const float Alf = Aleft[q];
                    const float pm  = fminf(dg, lf);
                    float best = fminf(up, pm);
                    // first-min parent select [diag, up, left] (= jnp.argmin order)
                    const bool p0 = (best == dg);
                    const bool p1 = (best == up);
                    const float Asel = p0 ? Adg : (p1 ? Aup : Alf);
                    if (q == 0) best = (best == INF) ? 0.0f : best;  // (0,0) seed only
                    const float cur  = best + cst0[q];
                    const float Acur = Asel + lc0[q];
                    dg = lf;  Adg = Alf;
                    up = cur; Aup = Acur;
                    cur0[q] = cur; Acur0[q] = Acur;
                }

                // ---- column c0+1 ----
                up = nb1; dg = nb0; Aup = na1; Adg = na0;
                #pragma unroll
                for (int q = 0; q < RR; ++q) {
                    const float lf  = cur0[q];
                    const float Alf = Acur0[q];
                    const float pm  = fminf(dg, lf);
                    const float best = fminf(up, pm);
                    const bool p0 = (best == dg);
                    const bool p1 = (best == up);
                    const float Asel = p0 ? Adg : (p1 ? Aup : Alf);
                    const float cur  = best + cst1[q];
                    const float Acur = Asel + lc1[q];
                    dg = lf;  Adg = Alf;
                    up = cur; Aup = Acur;
                    left[q] = cur; Aleft[q] = Acur;
                }

                bot0 = cur0[RR - 1];  Ab0 = Acur0[RR - 1];
                bot1 = left[RR - 1];  Ab1 = Aleft[RR - 1];
            }

            if (lane == 31) {
                if (warp < NWL - 1) {
                    sbD[par][ks][warp] = make_float4(bot0, bot1, pb1, 0.0f);
                    sbA[par][ks][warp] = make_float4(Ab0,  Ab1,  Apb, 0.0f);
                } else if (rank == 0) {
                    // cross-CTA producer: post slot s into rank1's smem
                    xpost(remD + (uint64_t)s * 16, bot0, bot1, pb1, s + 1);
                    xpost(remA + (uint64_t)s * 16, Ab0,  Ab1,  Apb, s + 1);
                }
            }

            // ---- pipeline: cost & loss terms for step s+1 (clamped group) ----
            {
                const int gn = min(max(s + 1 - sig, 0), NG - 1);
                const float2 t0 = txy[2 * gn];
                const float2 t1 = txy[2 * gn + 1];
                #pragma unroll
                for (int q = 0; q < RR; ++q) {
                    const float dx0 = px[q] - t0.x, dy0 = py[q] - t0.y;
                    cst0[q] = fsqrt_approx(fmaf(dx0, dx0, dy0 * dy0));
                    lc0[q]  = fmaf(fabsf(dy0), c1s, fabsf(dx0) * c0s);
                    const float dx1 = px[q] - t1.x, dy1 = py[q] - t1.y;
                    cst1[q] = fsqrt_approx(fmaf(dx1, dx1, dy1 * dy1));
                    lc1[q]  = fmaf(fabsf(dy1), c1s, fabsf(dx1) * c0s);
                }
            }
        }
        __syncthreads();
    }

    // ---- result: rank1 thread CT-1 holds A at (NN-1, MM-1) ----
    if (rank == 1 && tid == CT - 1) {
        g_loss[b] = Ab1;
        __threadfence();
        const int old = atomicAdd(&g_done, 1);
        if (old == BB - 1) {
            __threadfence();
            float t2 = 0.0f;
            #pragma unroll
            for (int x = 0; x < BB; ++x) t2 += g_loss[x];
            out[0] = t2;
            g_done = 0;   // self-reset for next graph replay
        }
    }

    // Keep DSMEM valid until both CTAs are done (producer tail writes).
    asm volatile("barrier.cluster.arrive.aligned;" ::: "memory");
    asm volatile("barrier.cluster.wait.aligned;" ::: "memory");
}

extern "C" void kernel_launch(void* const* d_in, const int* in_sizes, int n_in,
                              void* d_out, int out_size)
{
    const float* preds   = (const float*)d_in[0];
    const float* targs   = (const float*)d_in[1];
    const float* subcoef = (const float*)d_in[2];
    float* out = (float*)d_out;

    dtw_fused<<<BB * 2, CT>>>(preds, targs, subcoef, out);
}

// round 13
// speedup vs baseline: 1.3770x; 1.3770x over previous
#include <cuda_runtime.h>
#include <cuda_bf16.h>
#include <math.h>

// Problem constants (fixed by setup_inputs): B=32, N=M=1024, F=4
#define BB    32
#define NN    1024
#define MM    1024
#define BT    256             // block threads (8 warps -> 2 per SMSP)
#define RR    4               // rows per thread (256*4 = 1024)
#define NG    (MM / 2)        // 512 column groups (2 cols per group)
#define NWARP (BT / 32)       // 8

// Epoch-skew parameters: barrier every KS steps; warp boundary gap = KS.
#define KS      8
#define WSKEW   (32 + KS - 1)                 // 39: sigma = lane + 39*warp
#define SIGMAX  (31 + WSKEW * (NWARP - 1))    // 304
#define STEPS   (NG + SIGMAX)                 // 816 (multiple of 8; last cell at s=815)
#define EPOCHS  (STEPS / KS)                  // 102

__device__ float g_loss[BB];
__device__ int   g_done;     // zero-init; self-resetting each launch

__device__ __forceinline__ float fsqrt_approx(float x) {
    float r;
    asm("sqrt.approx.f32 %0, %1;" : "=f"(r) : "f"(x));
    return r;
}

__global__ __launch_bounds__(BT, 1)
void dtw_fused(const float* __restrict__ preds, const float* __restrict__ targs,
               const float* __restrict__ subcoef, float* __restrict__ out)
{
    const int b    = blockIdx.x;
    const int tid  = threadIdx.x;
    const int lane = tid & 31;
    const int warp = tid >> 5;
    const int sig  = lane + WSKEW * warp;     // thread skew
    const int wlo  = WSKEW * warp;            // warp-uniform active window
    const int whi  = wlo + 31 + NG;           // [wlo, whi)

    __shared__ float2 txy[MM];                // 8 KB target basis
    __shared__ float4 sb[2][KS][NWARP];       // handoff: {bot0, bot1, Ab0, Ab1}

    const float* pb = preds + (size_t)b * NN * 4;
    const float* tb = targs + (size_t)b * MM * 4;
    const float INF = __int_as_float(0x7f800000);
    const float c0s = subcoef[0];
    const float c1s = subcoef[1];

    // ---- init ----
    for (int idx = tid; idx < MM; idx += BT)
        txy[idx] = *(const float2*)(tb + (size_t)idx * 4);
    for (int idx = tid; idx < 2 * KS * NWARP; idx += BT)
        ((float4*)sb)[idx] = make_float4(INF, INF, 0.0f, 0.0f);

    float px[RR], py[RR], left[RR], Aleft[RR];
    #pragma unroll
    for (int q = 0; q < RR; ++q) {
        const float2 pv = *(const float2*)(pb + (size_t)(tid * RR + q) * 4);
        px[q] = pv.x; py[q] = pv.y;
        left[q]  = INF;
        Aleft[q] = 0.0f;
    }
    __syncthreads();

    // =====================================================================
    // Forward DP with loss propagation: thread owns rows 4t..4t+3; at step s
    // it processes column group g = s - sigma (columns 2g, 2g+1), carrying
    //   D[i,j] = cost(i,j) + min(D[i-1,j-1], D[i-1,j], D[i,j-1])
    //   A[i,j] = A[argmin parent] + |dx|*c0 + |dy|*c1   (path loss so far)
    // Parent select: first-min equality order [diag, up, left] = jnp.argmin.
    // In-warp handoff: 4 shfls; the diag operands (neighbor bot at col c0-1)
    // are CACHED from the previous step's nb1/na1 (identity: shfl(bot1@s-2)
    // == nb1@s-1; also holds across the KS-gap smem slots). Warp boundary:
    // one float4 slot, double-buffered per epoch, one barrier per KS steps.
    // DP body and the pipelined cost/loss generation are warp-uniformly
    // skipped outside [wlo, whi). Answer = A at (NN-1,MM-1), thread BT-1.
    // =====================================================================
    float bot0 = INF, bot1 = INF;
    float Ab0  = 0.0f, Ab1 = 0.0f;
    float cnb1 = INF, cna1 = 0.0f;            // cached diag operands

    float cst0[RR], cst1[RR], lc0[RR], lc1[RR];   // pipelined cost & loss terms
    {   // prologue: terms for step 0 (clamped group; only warp 0 uses them)
        const int gc = min(max(0 - sig, 0), NG - 1);
        const float2 t0 = txy[2 * gc];
        const float2 t1 = txy[2 * gc + 1];
        #pragma unroll
        for (int q = 0; q < RR; ++q) {
            const float dx0 = px[q] - t0.x, dy0 = py[q] - t0.y;
            cst0[q] = fsqrt_approx(fmaf(dx0, dx0, dy0 * dy0));
            lc0[q]  = fmaf(fabsf(dy0), c1s, fabsf(dx0) * c0s);
            const float dx1 = px[q] - t1.x, dy1 = py[q] - t1.y;
            cst1[q] = fsqrt_approx(fmaf(dx1, dx1, dy1 * dy1));
            lc1[q]  = fmaf(fabsf(dy1), c1s, fabsf(dx1) * c0s);
        }
    }

    for (int e = 0; e < EPOCHS; ++e) {
        const int par = e & 1;
        #pragma unroll
        for (int ks = 0; ks < KS; ++ks) {
            const int s = e * KS + ks;

            // ---- handoff (every step, cheap) ----
            float nb0 = __shfl_up_sync(0xffffffffu, bot0, 1);
            float nb1 = __shfl_up_sync(0xffffffffu, bot1, 1);
            float na0 = __shfl_up_sync(0xffffffffu, Ab0, 1);
            float na1 = __shfl_up_sync(0xffffffffu, Ab1, 1);
            if (lane == 0) {
                if (warp == 0) {
                    nb0 = INF; nb1 = INF; na0 = 0.0f; na1 = 0.0f;
                } else {
                    const float4 v = sb[par ^ 1][ks][warp - 1];  // producer step s-KS
                    nb0 = v.x; nb1 = v.y; na0 = v.z; na1 = v.w;
                }
            }

            // ---- DP body (warp-uniformly skipped outside active window) ----
            if (s >= wlo && s < whi) {
                const int g = s - sig;
                if ((unsigned)g < (unsigned)NG) {
                    // ---- column c0 (diag from cache) ----
                    float up = nb0, dg = cnb1, Aup = na0, Adg = cna1;
                    float cur0[RR], Acur0[RR];
                    #pragma unroll
                    for (int q = 0; q < RR; ++q) {
                        const float lf  = left[q];
                        const float Alf = Aleft[q];
                        const float pm  = fminf(dg, lf);
                        float best = fminf(up, pm);
                        const bool p0 = (best == dg);
                        const bool p1 = (best == up);
                        const float Asel = p0 ? Adg : (p1 ? Aup : Alf);
                        if (q == 0) best = (best == INF) ? 0.0f : best;  // (0,0) seed
                        const float cur  = best + cst0[q];
                        const float Acur = Asel + lc0[q];
                        dg = lf;  Adg = Alf;
                        up = cur; Aup = Acur;
                        cur0[q] = cur; Acur0[q] = Acur;
                    }

                    // ---- column c0+1 ----
                    up = nb1; dg = nb0; Aup = na1; Adg = na0;
                    #pragma unroll
                    for (int q = 0; q < RR; ++q) {
                        const float lf  = cur0[q];
                        const float Alf = Acur0[q];
                        const float pm  = fminf(dg, lf);
                        const float best = fminf(up, pm);
                        const bool p0 = (best == dg);
                        const bool p1 = (best == up);
                        const float Asel = p0 ? Adg : (p1 ? Aup : Alf);
                        const float cur  = best + cst1[q];
                        const float Acur = Asel + lc1[q];
                        dg = lf;  Adg = Alf;
                        up = cur; Aup = Acur;
                        left[q] = cur; Aleft[q] = Acur;
                    }

                    bot0 = cur0[RR - 1];  Ab0 = Acur0[RR - 1];
                    bot1 = left[RR - 1];  Ab1 = Aleft[RR - 1];
                }
            }

            if (lane == 31)
                sb[par][ks][warp] = make_float4(bot0, bot1, Ab0, Ab1);

            // update diag cache AFTER use
            cnb1 = nb1; cna1 = na1;

            // ---- pipelined cost/loss for step s+1 (uniform-guarded) ----
            if (s + 1 >= wlo && s + 1 < whi) {
                const int gn = min(max(s + 1 - sig, 0), NG - 1);
                const float2 t0 = txy[2 * gn];
                const float2 t1 = txy[2 * gn + 1];
                #pragma unroll
                for (int q = 0; q < RR; ++q) {
                    const float dx0 = px[q] - t0.x, dy0 = py[q] - t0.y;
                    cst0[q] = fsqrt_approx(fmaf(dx0, dx0, dy0 * dy0));
                    lc0[q]  = fmaf(fabsf(dy0), c1s, fabsf(dx0) * c0s);
                    const float dx1 = px[q] - t1.x, dy1 = py[q] - t1.y;
                    cst1[q] = fsqrt_approx(fmaf(dx1, dx1, dy1 * dy1));
                    lc1[q]  = fmaf(fabsf(dy1), c1s, fabsf(dx1) * c0s);
                }
            }
        }
        __syncthreads();
    }

    // ---- result: thread BT-1's Ab1 is A at (NN-1, MM-1) ----
    if (tid == BT - 1) {
        g_loss[b] = Ab1;
        __threadfence();
        const int old = atomicAdd(&g_done, 1);
        if (old == BB - 1) {
            __threadfence();
            float t2 = 0.0f;
            #pragma unroll
            for (int x = 0; x < BB; ++x) t2 += g_loss[x];
            out[0] = t2;
            g_done = 0;   // self-reset for next graph replay
        }
    }
}

extern "C" void kernel_launch(void* const* d_in, const int* in_sizes, int n_in,
                              void* d_out, int out_size)
{
    const float* preds   = (const float*)d_in[0];
    const float* targs   = (const float*)d_in[1];
    const float* subcoef = (const float*)d_in[2];
    float* out = (float*)d_out;

    dtw_fused<<<BB, BT>>>(preds, targs, subcoef, out);
}